// round 13
// baseline (speedup 1.0000x reference)
#include <cuda_runtime.h>

// SobelLoss: loss = sum_{voxels,d in {x,y,z}} |conv_d(moved - label)| / (3*N)
// Shapes: (B=2, 1, D=160, H=192, W=160) fp32, zero padding.
// Sobel separable: S=[1,2,1] smooth, D=[-1,0,1] derivative.
//
// NO shared memory in the hot loop. Each warp independently processes a
// 64-raw-col x-span (packed f32x2 per lane) x 2 output rows x one z-chunk.
// x-stencil via lane shuffles of register halves, y-stencil in registers,
// z-stencil via rolling p/q/r partials. Invalid lanes/cols removed with a
// bitwise mask fused into the abs (AND). 3 spans cover DIMX=160.

typedef unsigned long long ull;

#define DIMX 160
#define DIMY 192
#define DIMZ 160
#define NBATCH 2
#define PLANE (DIMY * DIMX)

#define NT 256
#define NW 8                    // warps per CTA
#define SPANS 3                 // x spans: 60 output cols each (64 raw)
#define ROWS_PER_CTA 16         // 8 warps x 2 output rows
#define YBLK (DIMY / ROWS_PER_CTA)     // 12
#define ZCHUNK 20
#define NZCH (DIMZ / ZCHUNK)           // 8
#define TOTAL_CTAS (SPANS * YBLK * NZCH * NBATCH)   // 576

// 1 / (3 * B*D*H*W) = 1 / 29491200
#define SCALE 3.3908420632258286e-08f
#define ABSM 0x7FFFFFFF7FFFFFFFULL

__device__ float    g_acc = 0.0f;
__device__ unsigned g_cnt = 0;

// ---- packed f32x2 helpers (Blackwell sm_103a) ----
__device__ __forceinline__ ull pk(float lo, float hi) {
    ull r; asm("mov.b64 %0, {%1, %2};" : "=l"(r) : "f"(lo), "f"(hi)); return r;
}
__device__ __forceinline__ void upk(ull p, float& lo, float& hi) {
    asm("mov.b64 {%0, %1}, %2;" : "=f"(lo), "=f"(hi) : "l"(p));
}
__device__ __forceinline__ ull padd(ull a, ull b) {
    ull r; asm("add.rn.f32x2 %0, %1, %2;" : "=l"(r) : "l"(a), "l"(b)); return r;
}
__device__ __forceinline__ ull pfma(ull a, ull b, ull c) {   // a*b + c
    ull r; asm("fma.rn.f32x2 %0, %1, %2, %3;" : "=l"(r) : "l"(a), "l"(b), "l"(c)); return r;
}

__launch_bounds__(NT, 4)
__global__ void sobel_loss_kernel(const float* __restrict__ moved,
                                  const float* __restrict__ label,
                                  float* __restrict__ out)
{
    const int tid  = threadIdx.x;
    const int w    = tid >> 5;
    const int lane = tid & 31;

    const int span = blockIdx.x;                       // 0..2
    const int Y    = blockIdx.y * ROWS_PER_CTA + 2 * w; // first output row
    const int b    = blockIdx.z / NZCH;
    const int z0   = (blockIdx.z % NZCH) * ZCHUNK;

    // lane's packed column pair: (xe, xe+1), xe even
    const int  xe  = span * 60 - 2 + 2 * lane;
    const bool okx = ((unsigned)xe < (unsigned)DIMX);

    const float* mb = moved + (size_t)b * DIMZ * PLANE;
    const float* lb = label + (size_t)b * DIMZ * PLANE;

    const ull C2  = pk(2.0f, 2.0f);
    const ull CM1 = pk(-1.0f, -1.0f);

    // z-invariant row offsets + predicates (raw rows Y-1 .. Y+2)
    int  off[4];
    bool okr[4];
    #pragma unroll
    for (int r = 0; r < 4; r++) {
        int gy = Y - 1 + r;
        okr[r] = okx && ((unsigned)gy < (unsigned)DIMY);
        off[r] = gy * DIMX + xe;
    }

    // output validity mask (both packed elems share it); also folds |.|
    const ull gmask = (lane >= 1 && lane <= 30 && okx) ? ABSM : 0ULL;

    // ---- fetch one diff plane into 4 packed row registers ----
    auto fetch = [&](int z, ull v[4]) {
        const bool zok = ((unsigned)z < (unsigned)DIMZ);
        const float* mz = mb + (size_t)z * PLANE;
        const float* lz = lb + (size_t)z * PLANE;
        ull m[4], l[4];
        #pragma unroll
        for (int r = 0; r < 4; r++) {
            m[r] = 0; l[r] = 0;
            if (zok && okr[r]) {
                m[r] = *(const ull*)(mz + off[r]);
                l[r] = *(const ull*)(lz + off[r]);
            }
        }
        #pragma unroll
        for (int r = 0; r < 4; r++) v[r] = pfma(l[r], CM1, m[r]);   // m - l
    };

    // ---- in-plane partials via shuffles (no smem) ----
    //   per raw row: s = x(-1)+2x(0)+x(+1), d = x(+1)-x(-1)
    //   left-shifted pair  = (hi(lane-1), lo)  -> 1 SHFL.32
    //   right-shifted pair = (hi, lo(lane+1))  -> 1 SHFL.32
    auto pqr = [&](const ull v[4],
                   ull& pA, ull& qA, ull& rA,
                   ull& pB, ull& qB, ull& rB) {
        ull s[4], d[4];
        #pragma unroll
        for (int r = 0; r < 4; r++) {
            float lo, hi; upk(v[r], lo, hi);
            float hl  = __shfl_up_sync(0xFFFFFFFFu, hi, 1);
            float ldn = __shfl_down_sync(0xFFFFFFFFu, lo, 1);
            ull vl = pk(hl, lo);
            ull vr = pk(hi, ldn);
            s[r] = padd(pfma(v[r], C2, vl), vr);
            d[r] = pfma(vl, CM1, vr);
        }
        pA = padd(pfma(d[1], C2, d[0]), d[2]);
        qA = pfma(s[0], CM1, s[2]);
        rA = padd(pfma(s[1], C2, s[0]), s[2]);
        pB = padd(pfma(d[2], C2, d[1]), d[3]);
        qB = pfma(s[1], CM1, s[3]);
        rB = padd(pfma(s[2], C2, s[1]), s[3]);
    };

    ull vA[4], vB[4];
    ull pA0,qA0,rA0, pA1,qA1,rA1, pB0,qB0,rB0, pB1,qB1,rB1;

    // prologue: partials for planes z0-1 and z0; prefetch plane z0+1
    fetch(z0 - 1, vA); pqr(vA, pA0,qA0,rA0, pB0,qB0,rB0);
    fetch(z0,     vA); pqr(vA, pA1,qA1,rA1, pB1,qB1,rB1);
    fetch(z0 + 1, vA);            // vA holds plane z0+1 for k=0

    ull acc = 0;

    // STEP(VN, VF, K): compute from VN (holds plane z0+K+1), emit output
    // plane z0+K, and fetch plane z0+K+2 into VF for the next step.
    // Fetch is needed whenever step K+1 exists: K <= ZCHUNK-2.   (FIXED)
    #define STEP(VN, VF, K)                                               \
        do {                                                              \
            if ((K) + 1 <= ZCHUNK - 1) fetch(z0 + (K) + 2, VF);           \
            ull pA2,qA2,rA2, pB2,qB2,rB2;                                 \
            pqr(VN, pA2,qA2,rA2, pB2,qB2,rB2);                            \
            ull Gx = padd(pfma(pA1, C2, pA0), pA2);                       \
            ull Gy = padd(pfma(qA1, C2, qA0), qA2);                       \
            ull Gz = pfma(rA0, CM1, rA2);                                 \
            acc = padd(acc, Gx & gmask);                                  \
            acc = padd(acc, Gy & gmask);                                  \
            acc = padd(acc, Gz & gmask);                                  \
            Gx = padd(pfma(pB1, C2, pB0), pB2);                           \
            Gy = padd(pfma(qB1, C2, qB0), qB2);                           \
            Gz = pfma(rB0, CM1, rB2);                                     \
            acc = padd(acc, Gx & gmask);                                  \
            acc = padd(acc, Gy & gmask);                                  \
            acc = padd(acc, Gz & gmask);                                  \
            pA0 = pA1; pA1 = pA2; qA0 = qA1; qA1 = qA2; rA0 = rA1; rA1 = rA2; \
            pB0 = pB1; pB1 = pB2; qB0 = qB1; qB1 = qB2; rB0 = rB1; rB1 = rB2; \
        } while (0)

    // main loop: alternate vA/vB so prefetch lands in the idle buffer
    for (int k = 0; k < ZCHUNK; k += 2) {
        STEP(vA, vB, k);       // compute from vA (plane z0+k+1), fetch into vB
        STEP(vB, vA, k + 1);   // compute from vB, fetch into vA
    }
    #undef STEP

    // ---- reduce: packed -> scalar -> warp -> block -> global ----
    float lo, hi;
    upk(acc, lo, hi);
    float a = lo + hi;

    #pragma unroll
    for (int o = 16; o > 0; o >>= 1)
        a += __shfl_down_sync(0xFFFFFFFFu, a, o);

    __shared__ float wsum[NW];
    if (lane == 0) wsum[w] = a;
    __syncthreads();

    if (tid < NW) {
        float v = wsum[tid];
        #pragma unroll
        for (int o = NW / 2; o > 0; o >>= 1)
            v += __shfl_down_sync((1u << NW) - 1u, v, o);
        if (tid == 0) {
            atomicAdd(&g_acc, v);
            __threadfence();
            if (atomicAdd(&g_cnt, 1u) == TOTAL_CTAS - 1) {
                __threadfence();
                *out = g_acc * SCALE;
                g_acc = 0.0f;      // reset for next (graph-replayed) launch
                g_cnt = 0;
            }
        }
    }
}

extern "C" void kernel_launch(void* const* d_in, const int* in_sizes, int n_in,
                              void* d_out, int out_size)
{
    const float* moved = (const float*)d_in[0];
    const float* label = (const float*)d_in[1];
    float* out = (float*)d_out;

    dim3 grid(SPANS, YBLK, NBATCH * NZCH);   // (3, 12, 16) = 576 CTAs
    sobel_loss_kernel<<<grid, NT>>>(moved, label, out);
}

// round 14
// speedup vs baseline: 1.0145x; 1.0145x over previous
#include <cuda_runtime.h>

// SobelLoss: loss = sum_{voxels,d in {x,y,z}} |conv_d(moved - label)| / (3*N)
// Shapes: (B=2, 1, D=160, H=192, W=160) fp32, zero padding.
// Sobel separable: S=[1,2,1] smooth, D=[-1,0,1] derivative.
// R9 architecture (128-thr CTA, 8/SM, packed f32x2 pqr, pair-packed smem)
// with wide LDG.128 fetch over a 40-col quad-aligned tile, NBUF=3,
// single-plane register prefetch, ZCHUNK=32 -> 1200 CTAs = one wave.

typedef unsigned long long ull;

#define DIMX 160
#define DIMY 192
#define DIMZ 160
#define NBATCH 2
#define PLANE (DIMY * DIMX)

#define TX 32
#define TY 4
#define NT (TX * TY)            // 128
#define OY 8                    // output rows per block (2 per thread)
#define ZCHUNK 32
#define NZCH (DIMZ / ZCHUNK)    // 5

#define TILE_W 40               // raw cols: gx in [32bx-4, 32bx+35], quad-aligned
#define NPAIR 5                 // 10 raw rows as 5 (even,odd) pairs
#define PLANE_ULL (NPAIR * TILE_W)   // 200 ull per plane buffer
#define NQ 10                   // col quads per pair-row
#define NSLOT (NPAIR * NQ)      // 50 fetch slots
#define NBUF 3

#define GRID_X (DIMX / TX)      // 5
#define GRID_Y (DIMY / OY)      // 24
#define TOTAL_CTAS (GRID_X * GRID_Y * NBATCH * NZCH)   // 1200

// 1 / (3 * B*D*H*W) = 1 / 29491200
#define SCALE 3.3908420632258286e-08f

__device__ float    g_acc = 0.0f;
__device__ unsigned g_cnt = 0;

// ---- packed f32x2 helpers (Blackwell sm_103a) ----
__device__ __forceinline__ ull pk(float lo, float hi) {
    ull r; asm("mov.b64 %0, {%1, %2};" : "=l"(r) : "f"(lo), "f"(hi)); return r;
}
__device__ __forceinline__ void upk(ull p, float& lo, float& hi) {
    asm("mov.b64 {%0, %1}, %2;" : "=f"(lo), "=f"(hi) : "l"(p));
}
__device__ __forceinline__ ull padd(ull a, ull b) {
    ull r; asm("add.rn.f32x2 %0, %1, %2;" : "=l"(r) : "l"(a), "l"(b)); return r;
}
__device__ __forceinline__ ull pfma(ull a, ull b, ull c) {   // a*b + c
    ull r; asm("fma.rn.f32x2 %0, %1, %2, %3;" : "=l"(r) : "l"(a), "l"(b), "l"(c)); return r;
}
// (hi(a), lo(b))
__device__ __forceinline__ ull pmid(ull a, ull b) {
    float alo, ahi, blo, bhi;
    upk(a, alo, ahi); upk(b, blo, bhi);
    return pk(ahi, blo);
}

__launch_bounds__(NT, 8)   // <=64 regs -> 8 CTAs/SM -> 1200 grid = ONE wave
__global__ void sobel_loss_kernel(const float* __restrict__ moved,
                                  const float* __restrict__ label,
                                  float* __restrict__ out)
{
    // plane buffer: ull[pair][rawcol] = float2{ raw row 2*pair, raw row 2*pair+1 }
    __shared__ __align__(16) ull tile2[NBUF][PLANE_ULL];

    const int tx  = threadIdx.x;
    const int ty  = threadIdx.y;
    const int tid = ty * TX + tx;

    const int b  = blockIdx.z / NZCH;
    const int z0 = (blockIdx.z % NZCH) * ZCHUNK;

    const int gy0 = blockIdx.y * OY - 1;   // global y of raw row 0
    const int gx0 = blockIdx.x * TX - 4;   // global x of raw col 0 (mult of 4)

    const float* mb = moved + (size_t)b * DIMZ * PLANE;
    const float* lb = label + (size_t)b * DIMZ * PLANE;

    const ull C2  = pk(2.0f, 2.0f);
    const ull CM1 = pk(-1.0f, -1.0f);

    // ---- fetch slot: (row pair, col quad) -> 2 rows x 4 cols per thread ----
    const int pair = tid / NQ;                  // 0..4 (tid < 50)
    const int q    = tid - pair * NQ;           // 0..9
    const int gx   = gx0 + 4 * q;               // mult of 4; quad fully in/out
    const int gyE  = gy0 + 2 * pair;
    const bool okx = (tid < NSLOT) && ((unsigned)gx < (unsigned)DIMX);
    const int offE = (okx && (unsigned)gyE       < (unsigned)DIMY) ? (gyE * DIMX + gx)       : -1;
    const int offO = (okx && (unsigned)(gyE + 1) < (unsigned)DIMY) ? ((gyE + 1) * DIMX + gx) : -1;
    const int wOff = pair * TILE_W + 4 * q;     // ull index; 32B aligned

    ull pr0, pr1, pr2, pr3;   // prefetched pair-packed diffs (4 raw cols)

    auto fetch = [&](int z) {
        float4 vE = make_float4(0.f, 0.f, 0.f, 0.f), vO = vE;
        if ((unsigned)z < (unsigned)DIMZ) {
            const float* mz = mb + (size_t)z * PLANE;
            const float* lz = lb + (size_t)z * PLANE;
            if (offE >= 0) {
                float4 m = *(const float4*)(mz + offE);
                float4 l = *(const float4*)(lz + offE);
                vE = make_float4(m.x - l.x, m.y - l.y, m.z - l.z, m.w - l.w);
            }
            if (offO >= 0) {
                float4 m = *(const float4*)(mz + offO);
                float4 l = *(const float4*)(lz + offO);
                vO = make_float4(m.x - l.x, m.y - l.y, m.z - l.z, m.w - l.w);
            }
        }
        pr0 = pk(vE.x, vO.x); pr1 = pk(vE.y, vO.y);
        pr2 = pk(vE.z, vO.z); pr3 = pk(vE.w, vO.w);
    };

    auto store = [&](int buf) {
        if (tid < NSLOT) {
            *(ulonglong2*)&tile2[buf][wOff]     = make_ulonglong2(pr0, pr1);
            *(ulonglong2*)&tile2[buf][wOff + 2] = make_ulonglong2(pr2, pr3);
        }
    };

    // ---- packed in-plane partials for this thread's output-row pair ----
    // output col tx (global 32bx+tx) -> raw local cols tx+3..tx+5
    auto compute_pqr = [&](int buf, ull& pP, ull& qP, ull& rP) {
        const ull* b0 = &tile2[buf][ty * TILE_W + tx + 3];
        ull a0 = b0[0],          c0 = b0[1],          e0 = b0[2];
        ull a1 = b0[TILE_W],     c1 = b0[TILE_W + 1], e1 = b0[TILE_W + 2];
        ull s0 = padd(pfma(c0, C2, a0), e0);
        ull d0 = pfma(a0, CM1, e0);
        ull s1 = padd(pfma(c1, C2, a1), e1);
        ull d1 = pfma(a1, CM1, e1);
        qP = pfma(s0, CM1, s1);
        rP = padd(pfma(pmid(s0, s1), C2, s0), s1);
        pP = padd(pfma(pmid(d0, d1), C2, d0), d1);
    };

    float acc = 0.0f;
    ull pP0, qP0, rP0, pP1, qP1, rP1;

    // ---- prologue: planes z0-1, z0, z0+1 -> buf (plane mod 3) ----
    fetch(z0 - 1); store((z0 + 2) % NBUF);   // z0-1 == z0+2 (mod 3)
    fetch(z0);     store( z0      % NBUF);
    fetch(z0 + 1); store((z0 + 1) % NBUF);
    __syncthreads();

    compute_pqr((z0 + 2) % NBUF, pP0, qP0, rP0);   // plane z0-1
    compute_pqr( z0      % NBUF, pP1, qP1, rP1);   // plane z0

    fetch(z0 + 2);   // prefetch: at iter k, registers hold plane z0+k+1

    int cBuf = (z0 + 1) % NBUF;   // buffer of compute plane z = z0+k
    int sBuf = (z0 + 2) % NBUF;   // store target (z+1) mod 3

    // ---- main loop: iter k (z=z0+k): barrier; store plane z+1 (over z-2);
    //      fetch plane z+2; compute pqr(plane z); emit output plane z-1 ----
    #pragma unroll 4
    for (int k = 1; k <= ZCHUNK; ++k) {
        __syncthreads();                     // all compute(z-1) done everywhere
        if (k < ZCHUNK) {
            store(sBuf);                     // plane z+1 -> its buffer
            if (k + 2 <= ZCHUNK) fetch(z0 + k + 2);
        }

        ull pP2, qP2, rP2;
        compute_pqr(cBuf, pP2, qP2, rP2);    // plane z

        ull Gx = padd(pfma(pP1, C2, pP0), pP2);
        ull Gy = padd(pfma(qP1, C2, qP0), qP2);
        ull Gz = pfma(rP0, CM1, rP2);

        float gxa, gxb, gya, gyb, gza, gzb;
        upk(Gx, gxa, gxb); upk(Gy, gya, gyb); upk(Gz, gza, gzb);
        acc += fabsf(gxa) + fabsf(gya);
        acc += fabsf(gza) + fabsf(gxb);
        acc += fabsf(gyb) + fabsf(gzb);

        pP0 = pP1; pP1 = pP2;
        qP0 = qP1; qP1 = qP2;
        rP0 = rP1; rP1 = rP2;
        cBuf = (cBuf == NBUF - 1) ? 0 : cBuf + 1;
        sBuf = (sBuf == NBUF - 1) ? 0 : sBuf + 1;
    }

    // ---- block reduction ----
    #pragma unroll
    for (int o = 16; o > 0; o >>= 1)
        acc += __shfl_down_sync(0xFFFFFFFFu, acc, o);

    __shared__ float wsum[NT / 32];
    if ((tid & 31) == 0) wsum[tid >> 5] = acc;
    __syncthreads();

    if (tid < (NT / 32)) {
        float v = wsum[tid];
        #pragma unroll
        for (int o = (NT / 64); o > 0; o >>= 1)
            v += __shfl_down_sync(0xFu, v, o);
        if (tid == 0) {
            atomicAdd(&g_acc, v);
            __threadfence();
            if (atomicAdd(&g_cnt, 1u) == TOTAL_CTAS - 1) {
                __threadfence();
                *out = g_acc * SCALE;
                g_acc = 0.0f;      // reset for next (graph-replayed) launch
                g_cnt = 0;
            }
        }
    }
}

extern "C" void kernel_launch(void* const* d_in, const int* in_sizes, int n_in,
                              void* d_out, int out_size)
{
    const float* moved = (const float*)d_in[0];
    const float* label = (const float*)d_in[1];
    float* out = (float*)d_out;

    dim3 grid(GRID_X, GRID_Y, NBATCH * NZCH);   // (5, 24, 10) = 1200 CTAs
    dim3 block(TX, TY);                         // (32, 4)
    sobel_loss_kernel<<<grid, block>>>(moved, label, out);
}

// round 15
// speedup vs baseline: 1.1459x; 1.1296x over previous
#include <cuda_runtime.h>

// SobelLoss: loss = sum_{voxels,d in {x,y,z}} |conv_d(moved - label)| / (3*N)
// Shapes: (B=2, 1, D=160, H=192, W=160) fp32, zero padding.
// Sobel separable: S=[1,2,1] smooth, D=[-1,0,1] derivative.
// R9 champion architecture (128-thr CTA @ 8/SM, 36-wide tile, pair-packed
// smem planes, packed f32x2 pqr, two-plane A/B register prefetch, NBUF=4)
// restructured to ONE __syncthreads per TWO z-planes, with packed
// abs-accumulate (AND + add.f32x2) in the emit path.

typedef unsigned long long ull;

#define DIMX 160
#define DIMY 192
#define DIMZ 160
#define NBATCH 2
#define PLANE (DIMY * DIMX)

#define TX 32
#define TY 4
#define NT (TX * TY)            // 128
#define OY 8                    // output rows per block (2 per thread)
#define ZCHUNK 32
#define NZCH (DIMZ / ZCHUNK)    // 5

#define TILE_W 36               // raw cols: gx in [32bx-2, 32bx+33] (8B aligned)
#define NPAIR 5                 // 10 raw rows as 5 (even,odd) pairs
#define PLANE_ULL (NPAIR * TILE_W)     // 180 ull per plane buffer
#define NSLOT (NPAIR * (TILE_W / 2))   // 90 fetch slots (col pairs)
#define NBUF 4

#define GRID_X (DIMX / TX)      // 5
#define GRID_Y (DIMY / OY)      // 24
#define TOTAL_CTAS (GRID_X * GRID_Y * NBATCH * NZCH)   // 1200

// 1 / (3 * B*D*H*W) = 1 / 29491200
#define SCALE 3.3908420632258286e-08f
#define ABSM 0x7FFFFFFF7FFFFFFFULL

__device__ float    g_acc = 0.0f;
__device__ unsigned g_cnt = 0;

// ---- packed f32x2 helpers (Blackwell sm_103a) ----
__device__ __forceinline__ ull pk(float lo, float hi) {
    ull r; asm("mov.b64 %0, {%1, %2};" : "=l"(r) : "f"(lo), "f"(hi)); return r;
}
__device__ __forceinline__ void upk(ull p, float& lo, float& hi) {
    asm("mov.b64 {%0, %1}, %2;" : "=f"(lo), "=f"(hi) : "l"(p));
}
__device__ __forceinline__ ull padd(ull a, ull b) {
    ull r; asm("add.rn.f32x2 %0, %1, %2;" : "=l"(r) : "l"(a), "l"(b)); return r;
}
__device__ __forceinline__ ull pfma(ull a, ull b, ull c) {   // a*b + c
    ull r; asm("fma.rn.f32x2 %0, %1, %2, %3;" : "=l"(r) : "l"(a), "l"(b), "l"(c)); return r;
}
// (hi(a), lo(b))
__device__ __forceinline__ ull pmid(ull a, ull b) {
    float alo, ahi, blo, bhi;
    upk(a, alo, ahi); upk(b, blo, bhi);
    return pk(ahi, blo);
}

__launch_bounds__(NT, 8)   // <=64 regs -> 8 CTAs/SM -> 1200 grid = ONE wave
__global__ void sobel_loss_kernel(const float* __restrict__ moved,
                                  const float* __restrict__ label,
                                  float* __restrict__ out)
{
    // plane buffer: [pair][col] = float2{ raw row 2*pair, raw row 2*pair+1 }
    __shared__ __align__(16) ull tile2[NBUF][PLANE_ULL];

    const int tx  = threadIdx.x;
    const int ty  = threadIdx.y;
    const int tid = ty * TX + tx;

    const int b  = blockIdx.z / NZCH;
    const int z0 = (blockIdx.z % NZCH) * ZCHUNK;

    const int gy0  = blockIdx.y * OY - 1;     // global y of tile row 0
    const int gxv0 = blockIdx.x * TX - 2;     // global x of tile col 0 (even)

    const float* mb = moved + (size_t)b * DIMZ * PLANE;
    const float* lb = label + (size_t)b * DIMZ * PLANE;

    const ull C2  = pk(2.0f, 2.0f);
    const ull CM1 = pk(-1.0f, -1.0f);

    // ---- fetch slot: (row pair, col pair) -> 2 rows x 2 cols per thread ----
    const int pair = tid / (TILE_W / 2);        // 0..4 (tid < 90)
    const int vc2  = tid - pair * (TILE_W / 2); // 0..17
    const int gx   = gxv0 + 2 * vc2;            // even, 8B aligned
    const int gyE  = gy0 + 2 * pair;
    const bool slotok = (tid < NSLOT) && ((unsigned)gx < (unsigned)DIMX);
    const int offE = (slotok && (unsigned)gyE       < (unsigned)DIMY) ? (gyE * DIMX + gx)       : -1;
    const int offO = (slotok && (unsigned)(gyE + 1) < (unsigned)DIMY) ? ((gyE + 1) * DIMX + gx) : -1;
    const int wOff = pair * TILE_W + 2 * vc2;   // ull index; 16B aligned

    // two prefetch register sets (A/B) -> 2 planes in flight
    ull preA0, preA1, preB0, preB1;

    auto fetch = [&](int z, ull& p0, ull& p1) {
        ull mE = 0, lE = 0, mO = 0, lO = 0;
        if ((unsigned)z < (unsigned)DIMZ) {
            const float* mz = mb + (size_t)z * PLANE;
            const float* lz = lb + (size_t)z * PLANE;
            if (offE >= 0) { mE = *(const ull*)(mz + offE); lE = *(const ull*)(lz + offE); }
            if (offO >= 0) { mO = *(const ull*)(mz + offO); lO = *(const ull*)(lz + offO); }
        }
        ull vE = pfma(lE, CM1, mE);   // moved - label, even row (2 cols)
        ull vO = pfma(lO, CM1, mO);   // odd row
        float e0, e1, o0, o1;
        upk(vE, e0, e1); upk(vO, o0, o1);
        p0 = pk(e0, o0);              // column L: (even,odd)
        p1 = pk(e1, o1);              // column R: (even,odd)
    };

    auto store = [&](int buf, ull p0, ull p1) {
        if (tid < NSLOT)
            *(ulonglong2*)&tile2[buf][wOff] = make_ulonglong2(p0, p1);
    };

    // ---- packed in-plane partials for this thread's output-row pair ----
    auto compute_pqr = [&](int buf, ull& pP, ull& qP, ull& rP) {
        const ull* b0 = &tile2[buf][ty * TILE_W + tx + 1];
        ull a0 = b0[0],          c0 = b0[1],          e0 = b0[2];
        ull a1 = b0[TILE_W],     c1 = b0[TILE_W + 1], e1 = b0[TILE_W + 2];
        ull s0 = padd(pfma(c0, C2, a0), e0);
        ull d0 = pfma(a0, CM1, e0);
        ull s1 = padd(pfma(c1, C2, a1), e1);
        ull d1 = pfma(a1, CM1, e1);
        qP = pfma(s0, CM1, s1);
        rP = padd(pfma(pmid(s0, s1), C2, s0), s1);
        pP = padd(pfma(pmid(d0, d1), C2, d0), d1);
    };

    ull pP0, qP0, rP0, pP1, qP1, rP1;

    // ---- prologue: planes z0-1, z0, z0+1, z0+2 -> buf (plane & 3) ----
    {
        ull t0, t1;
        fetch(z0 - 1, t0, t1); store((z0 + 3) & 3, t0, t1);  // (z0-1)&3 == (z0+3)&3
        fetch(z0,     t0, t1); store( z0      & 3, t0, t1);
        fetch(z0 + 1, t0, t1); store((z0 + 1) & 3, t0, t1);
        fetch(z0 + 2, t0, t1); store((z0 + 2) & 3, t0, t1);
    }
    __syncthreads();

    compute_pqr((z0 + 3) & 3, pP0, qP0, rP0);   // plane z0-1
    compute_pqr( z0      & 3, pP1, qP1, rP1);   // plane z0

    fetch(z0 + 3, preA0, preA1);   // stored at iter m=0
    fetch(z0 + 4, preB0, preB1);   // stored at iter m=0

    ull acc = 0;

    // ---- main loop: ONE barrier per TWO planes ----
    // iter m: barrier; store planes z0+2m+3 (A), z0+2m+4 (B) over planes
    //   z0+2m-1, z0+2m (both read before this barrier); fetch z0+2m+5/6;
    //   compute pqr(z0+2m+1) -> emit z0+2m; compute pqr(z0+2m+2) -> emit z0+2m+1.
    #define EMIT(P2, Q2, R2)                                               \
        do {                                                               \
            ull Gx = padd(pfma(pP1, C2, pP0), P2);                         \
            ull Gy = padd(pfma(qP1, C2, qP0), Q2);                         \
            ull Gz = pfma(rP0, CM1, R2);                                   \
            acc = padd(acc, Gx & ABSM);                                    \
            acc = padd(acc, Gy & ABSM);                                    \
            acc = padd(acc, Gz & ABSM);                                    \
            pP0 = pP1; pP1 = P2; qP0 = qP1; qP1 = Q2; rP0 = rP1; rP1 = R2; \
        } while (0)

    #pragma unroll 2
    for (int m = 0; m < ZCHUNK / 2; ++m) {
        const int zc = z0 + 2 * m + 1;    // first compute plane this iter
        __syncthreads();
        if (m < ZCHUNK / 2 - 1) {
            store((zc + 2) & 3, preA0, preA1);   // plane z0+2m+3
            store((zc + 3) & 3, preB0, preB1);   // plane z0+2m+4
        }
        if (m < ZCHUNK / 2 - 2) {
            fetch(zc + 4, preA0, preA1);         // plane z0+2m+5
            fetch(zc + 5, preB0, preB1);         // plane z0+2m+6
        }

        ull p2, q2, r2;
        compute_pqr(zc & 3, p2, q2, r2);         // plane z0+2m+1
        EMIT(p2, q2, r2);                        // output plane z0+2m
        compute_pqr((zc + 1) & 3, p2, q2, r2);   // plane z0+2m+2
        EMIT(p2, q2, r2);                        // output plane z0+2m+1
    }
    #undef EMIT

    // ---- reduce: packed -> scalar -> warp -> block -> global ----
    float lo, hi;
    upk(acc, lo, hi);
    float a = lo + hi;

    #pragma unroll
    for (int o = 16; o > 0; o >>= 1)
        a += __shfl_down_sync(0xFFFFFFFFu, a, o);

    __shared__ float wsum[NT / 32];
    if ((tid & 31) == 0) wsum[tid >> 5] = a;
    __syncthreads();

    if (tid < (NT / 32)) {
        float v = wsum[tid];
        #pragma unroll
        for (int o = (NT / 64); o > 0; o >>= 1)
            v += __shfl_down_sync(0xFu, v, o);
        if (tid == 0) {
            atomicAdd(&g_acc, v);
            __threadfence();
            if (atomicAdd(&g_cnt, 1u) == TOTAL_CTAS - 1) {
                __threadfence();
                *out = g_acc * SCALE;
                g_acc = 0.0f;      // reset for next (graph-replayed) launch
                g_cnt = 0;
            }
        }
    }
}

extern "C" void kernel_launch(void* const* d_in, const int* in_sizes, int n_in,
                              void* d_out, int out_size)
{
    const float* moved = (const float*)d_in[0];
    const float* label = (const float*)d_in[1];
    float* out = (float*)d_out;

    dim3 grid(GRID_X, GRID_Y, NBATCH * NZCH);   // (5, 24, 10) = 1200 CTAs
    dim3 block(TX, TY);                         // (32, 4)
    sobel_loss_kernel<<<grid, block>>>(moved, label, out);
}